// round 8
// baseline (speedup 1.0000x reference)
#include <cuda_runtime.h>
#include <cstdint>
#include <stdint.h>

#define B_SZ   256
#define T_SZ   2048
#define N_SZ   128
#define NPAIRS (B_SZ * T_SZ)   // 524288

// Solve workspace: 128 rows x 132 floats (cols 0..127 = I+A, 128/129 = RHS)
#define WROW   132
#define WROW4  33
#define BSROW  129

// Scratch (device globals — no allocation allowed)
__device__ __align__(16) float g_h[NPAIRS * 2];   // hidden, [t][b] float2 layout
__device__ __align__(16) float g_q0[N_SZ];        // Q[:,0]
__device__ __align__(16) float g_q1[N_SZ];        // Q[:,1]

__device__ __forceinline__ float fast_rcp(float x) {
    float r;
    asm("rcp.approx.f32 %0, %1;" : "=f"(r) : "f"(x));
    return r;
}

// ---------------------------------------------------------------------------
// Phase 1 (256 threads/block):
//   block 0:     Cayley solve — 2 threads per row (parity-split float4 groups)
//   blocks 1..2: leaky RNN — threads 0..127 each run one sequence,
//                streaming their own contiguous 24KB of u via __ldg rotation
// ---------------------------------------------------------------------------
__global__ void __launch_bounds__(256) phase1_kernel(
        const float* __restrict__ u,
        const float* __restrict__ matB,
        const float* __restrict__ wIn,
        const float* __restrict__ wRec) {
    extern __shared__ float smem[];
    const int tid = threadIdx.x;

    if (blockIdx.x == 0) {
        // ================= Cayley solve =================
        float*  Wf = smem;                      // [128][132]
        float4* W4 = (float4*)smem;             // [128][33]
        float*  Bs = smem + N_SZ * WROW;        // [128][129]
        __shared__ float z0s[N_SZ], z1s[N_SZ];
        const int i    = tid & 127;             // row
        const int half = tid >> 7;              // 0/1: parity of float4 groups

        // stage matB (coalesced float4), all 256 threads
        for (int idx = tid; idx < N_SZ * 32; idx += 256) {
            int r = idx >> 5, c4 = idx & 31;
            float4 v = ((const float4*)matB)[r * 32 + c4];
            float* dst = Bs + r * BSROW + c4 * 4;
            dst[0] = v.x; dst[1] = v.y; dst[2] = v.z; dst[3] = v.w;
        }
        __syncthreads();

        // build augmented [I+A | e0 e1]  (half 0 threads only)
        if (half == 0) {
            float* wr = Wf + i * WROW;
            #pragma unroll 4
            for (int j = 0; j < N_SZ; j++) {
                float a = Bs[i * BSROW + j] - Bs[j * BSROW + i];
                wr[j] = (i == j ? 1.0f : 0.0f) + a;
            }
            wr[128] = (i == 0) ? 1.0f : 0.0f;
            wr[129] = (i == 1) ? 1.0f : 0.0f;
            wr[130] = 0.0f; wr[131] = 0.0f;
        }

        // forward elimination: one barrier per pivot, 2 threads per row
        for (int k = 0; k < N_SZ; k++) {
            __syncthreads();
            if (i > k) {
                float rinv = fast_rcp(Wf[k * WROW + k]);
                float f = Wf[i * WROW + k] * rinv;
                float4*       wr = W4 + i * WROW4;
                const float4* pr = W4 + k * WROW4;
                int g0 = k >> 2;
                int gs = (g0 & ~1) | half;       // first group with parity==half
                if (gs < g0) gs += 2;
                #pragma unroll 2
                for (int g = gs; g < WROW4; g += 2) {
                    float4 a = wr[g];
                    float4 p = pr[g];
                    a.x = fmaf(-f, p.x, a.x);
                    a.y = fmaf(-f, p.y, a.y);
                    a.z = fmaf(-f, p.z, a.z);
                    a.w = fmaf(-f, p.w, a.w);
                    wr[g] = a;
                }
            }
        }

        // back substitution (2 RHS), half-0 threads
        for (int k = N_SZ - 1; k >= 0; k--) {
            __syncthreads();
            if (half == 0) {
                float rinv = fast_rcp(Wf[k * WROW + k]);
                float zk0 = Wf[k * WROW + 128] * rinv;
                float zk1 = Wf[k * WROW + 129] * rinv;
                if (i < k) {
                    float a = Wf[i * WROW + k];
                    Wf[i * WROW + 128] = fmaf(-a, zk0, Wf[i * WROW + 128]);
                    Wf[i * WROW + 129] = fmaf(-a, zk1, Wf[i * WROW + 129]);
                } else if (i == k) {
                    z0s[k] = zk0;
                    z1s[k] = zk1;
                }
            }
        }
        __syncthreads();

        // q_r = (I - A) z_r
        if (half == 0) {
            float q0 = z0s[i], q1 = z1s[i];
            #pragma unroll 4
            for (int k = 0; k < N_SZ; k++) {
                float a = Bs[i * BSROW + k] - Bs[k * BSROW + i];
                q0 = fmaf(-a, z0s[k], q0);
                q1 = fmaf(-a, z1s[k], q1);
            }
            g_q0[i] = q0;
            g_q1[i] = q1;
        }
    } else {
        // ================= Leaky RNN: one thread per sequence ===============
        if (tid >= 128) return;
        const int seq = (blockIdx.x - 1) * 128 + tid;

        // fold ALPHA=0.1 into the weights
        const float W00 = 0.1f * wRec[0], W01 = 0.1f * wRec[1];
        const float W10 = 0.1f * wRec[2], W11 = 0.1f * wRec[3];
        const float I00 = 0.1f * wIn[0], I01 = 0.1f * wIn[1], I02 = 0.1f * wIn[2];
        const float I10 = 0.1f * wIn[3], I11 = 0.1f * wIn[4], I12 = 0.1f * wIn[5];

        const float4* up4 = (const float4*)(u + (size_t)seq * T_SZ * 3); // 1536 f4
        float2* hp = (float2*)g_h;

        float y0 = 0.0f, y1 = 0.0f;

        // step macro: 12-cycle dependent chain, input FMAs off-chain
        #define RNN_STEP(X0, X1, X2, TT)                                        \
            {                                                                   \
                float c0 = fmaf(I00, (X0), fmaf(I01, (X1), I02 * (X2)));        \
                float c1 = fmaf(I10, (X0), fmaf(I11, (X1), I12 * (X2)));        \
                float a0 = fmaf(0.9f, y0, c0);                                  \
                float a1 = fmaf(0.9f, y1, c1);                                  \
                float r0 = fmaxf(y0, 0.0f);                                     \
                float r1 = fmaxf(y1, 0.0f);                                     \
                float t0 = fmaf(W00, r0, a0);                                   \
                float t1 = fmaf(W10, r0, a1);                                   \
                y0 = fmaf(W01, r1, t0);                                         \
                y1 = fmaf(W11, r1, t1);                                         \
                hp[(TT) * B_SZ + seq] = make_float2(y0, y1);                    \
            }

        // 8 steps from a 6-float4 register group
        #define RNN_G8(b0, b1, b2, b3, b4, b5, TB)                              \
            {                                                                   \
                RNN_STEP(b0.x, b0.y, b0.z, (TB) + 0);                           \
                RNN_STEP(b0.w, b1.x, b1.y, (TB) + 1);                           \
                RNN_STEP(b1.z, b1.w, b2.x, (TB) + 2);                           \
                RNN_STEP(b2.y, b2.z, b2.w, (TB) + 3);                           \
                RNN_STEP(b3.x, b3.y, b3.z, (TB) + 4);                           \
                RNN_STEP(b3.w, b4.x, b4.y, (TB) + 5);                           \
                RNN_STEP(b4.z, b4.w, b5.x, (TB) + 6);                           \
                RNN_STEP(b5.y, b5.z, b5.w, (TB) + 7);                           \
            }

        #define LOAD6(P0, P1, P2, P3, P4, P5, GRP)                              \
            {                                                                   \
                const float4* p = up4 + (GRP) * 6;                              \
                P0 = __ldg(p + 0); P1 = __ldg(p + 1); P2 = __ldg(p + 2);        \
                P3 = __ldg(p + 3); P4 = __ldg(p + 4); P5 = __ldg(p + 5);        \
            }

        float4 A0, A1, A2, A3, A4, A5;
        float4 B0, B1, B2, B3, B4, B5;
        float4 C0, C1, C2, C3, C4, C5;

        LOAD6(A0, A1, A2, A3, A4, A5, 0);
        LOAD6(B0, B1, B2, B3, B4, B5, 1);

        // 256 groups of 8 steps; rotate A/B/C, loads run 2-3 groups ahead
        #pragma unroll 1
        for (int g = 0; g < 255; g += 3) {
            LOAD6(C0, C1, C2, C3, C4, C5, g + 2);
            RNN_G8(A0, A1, A2, A3, A4, A5, (g + 0) * 8);
            LOAD6(A0, A1, A2, A3, A4, A5, g + 3);
            RNN_G8(B0, B1, B2, B3, B4, B5, (g + 1) * 8);
            if (g + 4 < 256) LOAD6(B0, B1, B2, B3, B4, B5, g + 4);
            RNN_G8(C0, C1, C2, C3, C4, C5, (g + 2) * 8);
        }
        RNN_G8(A0, A1, A2, A3, A4, A5, 255 * 8);   // last group

        #undef LOAD6
        #undef RNN_G8
        #undef RNN_STEP
    }
}

// ---------------------------------------------------------------------------
// Phase 2: out[b,t,:] = h0 * q0[:] + h1 * q1[:]
// Warp task q = b*2048 + t (t fastest) -> sequential 2KB runs per warp task.
// ---------------------------------------------------------------------------
__global__ void __launch_bounds__(256, 8) expand_kernel(float* __restrict__ out) {
    const int lane = threadIdx.x & 31;
    const int wid  = ((int)blockIdx.x * (int)blockDim.x + (int)threadIdx.x) >> 5;
    const int nw   = ((int)gridDim.x * (int)blockDim.x) >> 5;

    const float4 q0 = ((const float4*)g_q0)[lane];
    const float4 q1 = ((const float4*)g_q1)[lane];
    const float2* hp = (const float2*)g_h;
    float4* o = (float4*)out;

    const int ntask = NPAIRS / 4;   // 131072 warp-tasks of 4 timesteps
    for (int task = wid; task < ntask; task += nw) {
        int q = task << 2;          // q = b*2048 + t
        int b = q >> 11;
        int t = q & (T_SZ - 1);

        float2 h0 = hp[(t + 0) * B_SZ + b];
        float2 h1 = hp[(t + 1) * B_SZ + b];
        float2 h2 = hp[(t + 2) * B_SZ + b];
        float2 h3 = hp[(t + 3) * B_SZ + b];

        size_t base = (size_t)q * 32 + lane;
        float4 v;
        v.x = fmaf(h0.x, q0.x, h0.y * q1.x);
        v.y = fmaf(h0.x, q0.y, h0.y * q1.y);
        v.z = fmaf(h0.x, q0.z, h0.y * q1.z);
        v.w = fmaf(h0.x, q0.w, h0.y * q1.w);
        __stcs(&o[base], v);
        v.x = fmaf(h1.x, q0.x, h1.y * q1.x);
        v.y = fmaf(h1.x, q0.y, h1.y * q1.y);
        v.z = fmaf(h1.x, q0.z, h1.y * q1.z);
        v.w = fmaf(h1.x, q0.w, h1.y * q1.w);
        __stcs(&o[base + 32], v);
        v.x = fmaf(h2.x, q0.x, h2.y * q1.x);
        v.y = fmaf(h2.x, q0.y, h2.y * q1.y);
        v.z = fmaf(h2.x, q0.z, h2.y * q1.z);
        v.w = fmaf(h2.x, q0.w, h2.y * q1.w);
        __stcs(&o[base + 64], v);
        v.x = fmaf(h3.x, q0.x, h3.y * q1.x);
        v.y = fmaf(h3.x, q0.y, h3.y * q1.y);
        v.z = fmaf(h3.x, q0.z, h3.y * q1.z);
        v.w = fmaf(h3.x, q0.w, h3.y * q1.w);
        __stcs(&o[base + 96], v);
    }
}

// ---------------------------------------------------------------------------
extern "C" void kernel_launch(void* const* d_in, const int* in_sizes, int n_in,
                              void* d_out, int out_size) {
    // Identify inputs by element count:
    // u = 1572864, matB = 16384, wIn = 6, wRec = 4
    const float *u = nullptr, *matB = nullptr, *wIn = nullptr, *wRec = nullptr;
    for (int i = 0; i < n_in; i++) {
        switch (in_sizes[i]) {
            case 1572864: u    = (const float*)d_in[i]; break;
            case 16384:   matB = (const float*)d_in[i]; break;
            case 6:       wIn  = (const float*)d_in[i]; break;
            case 4:       wRec = (const float*)d_in[i]; break;
        }
    }

    const int smem = (N_SZ * WROW + N_SZ * BSROW) * (int)sizeof(float); // 133632
    cudaFuncSetAttribute(phase1_kernel,
                         cudaFuncAttributeMaxDynamicSharedMemorySize, smem);

    // block 0: solve;  blocks 1..2: RNN (128 sequences each, no loaders)
    phase1_kernel<<<3, 256, smem>>>(u, matB, wIn, wRec);

    // expand: write-bandwidth bound
    expand_kernel<<<1184, 256>>>((float*)d_out);
}